// round 12
// baseline (speedup 1.0000x reference)
#include <cuda_runtime.h>
#include <math.h>

#define BATCH   16384
#define N_CAT   26
#define N_CONT  13
#define EDIM    128
#define VOCAB   100000
#define N_ROWS  27            // N_CAT + 1
#define N_PAIRS 351           // 27*26/2
#define TOP_IN  479           // 351 + 128
#define X0_LD   480           // padded stride

// ------------------------- scratch (device globals) -------------------------
__device__ float g_h1[BATCH * 512];     // bottom L1 out; reused as t3 (B x 512)
__device__ float g_h2[BATCH * 256];     // bottom L2 out; reused as t4 (B x 256)
__device__ float g_dense[BATCH * 128];  // bottom MLP output
__device__ float g_x0[BATCH * X0_LD];   // top MLP input (351 inter + 128 dense + 1 pad)
__device__ float g_t1[BATCH * 1024];
__device__ float g_t2[BATCH * 1024];
__device__ float g_Wt1p[X0_LD * 1024];  // Wt1 padded K 479 -> 480 (row 479 = 0)
__device__ int   g_is64;

// ------------------------- f32x2 packed math helpers ------------------------
__device__ __forceinline__ unsigned long long pack2(float x, float y) {
    unsigned long long d;
    asm("mov.b64 %0, {%1, %2};" : "=l"(d) : "f"(x), "f"(y));
    return d;
}
__device__ __forceinline__ unsigned long long ffma2(unsigned long long a,
                                                    unsigned long long b,
                                                    unsigned long long c) {
    unsigned long long d;
    asm("fma.rn.f32x2 %0, %1, %2, %3;" : "=l"(d) : "l"(a), "l"(b), "l"(c));
    return d;
}

// ------------------------- idx dtype detector -------------------------------
// If cat_idx is int64 (values < 100000), every odd 32-bit word of the buffer
// is 0. If it is int32, odd words are random indices in [0, 100000) -> the
// probability all 2048 are zero is ~0.
__global__ void detect_idx_kernel(const unsigned int* __restrict__ w) {
    __shared__ int ok;
    if (threadIdx.x == 0) ok = 1;
    __syncthreads();
    bool bad = false;
    for (int i = threadIdx.x; i < 2048; i += 256)
        if (w[2 * i + 1] != 0u) bad = true;
    if (bad) ok = 0;
    __syncthreads();
    if (threadIdx.x == 0) g_is64 = ok;
}

// ------------------------- bottom MLP layer 1 (K=13) ------------------------
// 4 rows per block, 128 threads; W row chunks reused across the 4 rows.
__global__ void dense1_kernel(const float* __restrict__ X,
                              const float* __restrict__ W,
                              const float* __restrict__ bias) {
    __shared__ float xs[4][N_CONT];
    const int row0 = blockIdx.x * 4;
    const int t = threadIdx.x;
    if (t < 4 * N_CONT) xs[t / N_CONT][t % N_CONT] = X[(size_t)(row0 + t / N_CONT) * N_CONT + (t % N_CONT)];
    __syncthreads();

    const int n0 = t * 4;
    float4 acc[4];
    #pragma unroll
    for (int r = 0; r < 4; r++) acc[r] = make_float4(0.f, 0.f, 0.f, 0.f);

    #pragma unroll
    for (int k = 0; k < N_CONT; k++) {
        float4 w = *(const float4*)&W[k * 512 + n0];
        #pragma unroll
        for (int r = 0; r < 4; r++) {
            float xk = xs[r][k];
            acc[r].x += xk * w.x; acc[r].y += xk * w.y;
            acc[r].z += xk * w.z; acc[r].w += xk * w.w;
        }
    }
    float4 bb = *(const float4*)&bias[n0];
    #pragma unroll
    for (int r = 0; r < 4; r++) {
        float4 v;
        v.x = fmaxf(acc[r].x + bb.x, 0.f);
        v.y = fmaxf(acc[r].y + bb.y, 0.f);
        v.z = fmaxf(acc[r].z + bb.z, 0.f);
        v.w = fmaxf(acc[r].w + bb.w, 0.f);
        *(float4*)&g_h1[(size_t)(row0 + r) * 512 + n0] = v;
    }
}

// ------------------------- Wt1 pad kernel ------------------------------------
__global__ void pad_wt1_kernel(const float* __restrict__ W) {
    int i = blockIdx.x * 256 + threadIdx.x;
    if (i < X0_LD * 1024)
        g_Wt1p[i] = (i < TOP_IN * 1024) ? W[i] : 0.f;
}

// ------------------------- fused gather + interactions ----------------------
// One block per batch row. Gathers 26 embedding rows + dense row into smem,
// then computes the 351 upper-triangle dot products straight into g_x0.
__global__ void interact_kernel(const void* __restrict__ cat,
                                const float* __restrict__ emb) {
    __shared__ float Zs[N_ROWS * EDIM];   // 13824 B
    const int b = blockIdx.x;
    const int t = threadIdx.x;            // 384 threads = 12 warps
    const int lane = t & 31;
    const int warp = t >> 5;
    const int is64 = g_is64;

    for (int row = warp; row < N_ROWS; row += 12) {
        const float4* src;
        if (row < N_CAT) {
            long long idx;
            size_t e = (size_t)b * N_CAT + row;
            if (is64) idx = ((const long long*)cat)[e];
            else      idx = (long long)((const int*)cat)[e];
            src = (const float4*)(emb + ((long long)row * VOCAB + idx) * EDIM);
        } else {
            src = (const float4*)(g_dense + (size_t)b * EDIM);
        }
        ((float4*)(Zs + row * EDIM))[lane] = src[lane];
    }
    __syncthreads();

    if (t < N_PAIRS) {
        // decode pair index -> (i, j), row-major upper triangle k=1
        int i = 0, rem = t, rl = N_CAT;
        while (rem >= rl) { rem -= rl; rl--; i++; }
        int j = i + 1 + rem;
        const float4* zi = (const float4*)(Zs + i * EDIM);
        const float4* zj = (const float4*)(Zs + j * EDIM);
        float acc = 0.f;
        #pragma unroll
        for (int e = 0; e < EDIM / 4; e++) {
            float4 a = zi[e], c = zj[e];
            acc += a.x * c.x + a.y * c.y + a.z * c.z + a.w * c.w;
        }
        g_x0[(size_t)b * X0_LD + t] = acc;
    } else if (t == N_PAIRS) {
        g_x0[(size_t)b * X0_LD + (X0_LD - 1)] = 0.f;  // pad column
    }
}

// ------------------------- SGEMM (f32x2 packed) ------------------------------
// C[M,N] = relu?(A[M,K] @ W[K,N] + bias). 128x128x16 tile, 256 thr, 8x8/thread
// via 8x4 packed f32x2 accumulators. Requires K%16==0, N%128==0, M%128==0.
__global__ __launch_bounds__(256, 2)
void sgemm_bias_act(const float* __restrict__ A, int lda,
                    const float* __restrict__ Wg,
                    const float* __restrict__ bias,
                    float* __restrict__ C, int ldc,
                    float* __restrict__ C2, int ldc2,
                    int N, int K, int relu) {
    __shared__ unsigned long long As2[16][128];  // A values pre-packed (a,a)
    __shared__ unsigned long long Bs2[16][64];   // B pairs (n, n+1)

    const int tid = threadIdx.x;
    const int tx = tid & 15;
    const int ty = tid >> 4;
    const int rm = blockIdx.y * 128;
    const int bn = blockIdx.x * 128;

    unsigned long long acc[8][4];
    #pragma unroll
    for (int i = 0; i < 8; i++)
        #pragma unroll
        for (int jj = 0; jj < 4; jj++) acc[i][jj] = 0ull;

    const int ar = tid >> 2;
    const int akq = (tid & 3) << 2;
    const int bkr = tid >> 5;
    const int bn4 = (tid & 31) << 2;

    for (int k0 = 0; k0 < K; k0 += 16) {
        #pragma unroll
        for (int l = 0; l < 2; l++) {
            int rr = ar + l * 64;
            float4 a = *(const float4*)(A + (size_t)(rm + rr) * lda + k0 + akq);
            As2[akq + 0][rr] = pack2(a.x, a.x);
            As2[akq + 1][rr] = pack2(a.y, a.y);
            As2[akq + 2][rr] = pack2(a.z, a.z);
            As2[akq + 3][rr] = pack2(a.w, a.w);
        }
        #pragma unroll
        for (int l = 0; l < 2; l++) {
            int kk = bkr + l * 8;
            float4 bv = *(const float4*)(Wg + (size_t)(k0 + kk) * N + bn + bn4);
            *(float4*)((float*)&Bs2[kk][0] + bn4) = bv;
        }
        __syncthreads();

        #pragma unroll
        for (int k = 0; k < 16; k++) {
            ulonglong2 a0 = *(const ulonglong2*)&As2[k][ty * 8 + 0];
            ulonglong2 a1 = *(const ulonglong2*)&As2[k][ty * 8 + 2];
            ulonglong2 a2 = *(const ulonglong2*)&As2[k][ty * 8 + 4];
            ulonglong2 a3 = *(const ulonglong2*)&As2[k][ty * 8 + 6];
            ulonglong2 b0 = *(const ulonglong2*)&Bs2[k][tx * 4 + 0];
            ulonglong2 b1 = *(const ulonglong2*)&Bs2[k][tx * 4 + 2];
            unsigned long long ra[8] = {a0.x, a0.y, a1.x, a1.y, a2.x, a2.y, a3.x, a3.y};
            unsigned long long rb[4] = {b0.x, b0.y, b1.x, b1.y};
            #pragma unroll
            for (int i = 0; i < 8; i++)
                #pragma unroll
                for (int jj = 0; jj < 4; jj++)
                    acc[i][jj] = ffma2(ra[i], rb[jj], acc[i][jj]);
        }
        __syncthreads();
    }

    #pragma unroll
    for (int i = 0; i < 8; i++) {
        int row = rm + ty * 8 + i;
        #pragma unroll
        for (int jj = 0; jj < 4; jj++) {
            int c0 = bn + tx * 8 + jj * 2;
            float lo = __uint_as_float((unsigned)(acc[i][jj] & 0xffffffffull));
            float hi = __uint_as_float((unsigned)(acc[i][jj] >> 32));
            float v0 = lo + bias[c0];
            float v1 = hi + bias[c0 + 1];
            if (relu) { v0 = fmaxf(v0, 0.f); v1 = fmaxf(v1, 0.f); }
            C[(size_t)row * ldc + c0]     = v0;
            C[(size_t)row * ldc + c0 + 1] = v1;
            if (C2) {
                C2[(size_t)row * ldc2 + c0]     = v0;
                C2[(size_t)row * ldc2 + c0 + 1] = v1;
            }
        }
    }
}

// ------------------------- final dot + sigmoid -------------------------------
__global__ void final_kernel(const float* __restrict__ Wo,
                             const float* __restrict__ bo,
                             float* __restrict__ out) {
    __shared__ float ws[256];
    const int t = threadIdx.x;
    ws[t] = Wo[t];
    __syncthreads();
    const int lane = t & 31;
    const int warp = t >> 5;
    const int row = blockIdx.x * 8 + warp;
    const float* a = g_h2 + (size_t)row * 256;   // t4 lives in g_h2
    float acc = 0.f;
    #pragma unroll
    for (int q = 0; q < 8; q++)
        acc += a[lane + 32 * q] * ws[lane + 32 * q];
    #pragma unroll
    for (int off = 16; off; off >>= 1)
        acc += __shfl_down_sync(0xffffffffu, acc, off);
    if (lane == 0) {
        float x = acc + bo[0];
        out[row] = 1.f / (1.f + expf(-x));
    }
}

// ------------------------- launch ------------------------------------------
extern "C" void kernel_launch(void* const* d_in, const int* in_sizes, int n_in,
                              void* d_out, int out_size) {
    const float* dense_x = (const float*)d_in[0];
    const void*  cat_idx = d_in[1];
    const float* emb     = (const float*)d_in[2];
    const float* Wd1 = (const float*)d_in[3];
    const float* bd1 = (const float*)d_in[4];
    const float* Wd2 = (const float*)d_in[5];
    const float* bd2 = (const float*)d_in[6];
    const float* Wdf = (const float*)d_in[7];
    const float* bdf = (const float*)d_in[8];
    const float* Wt1 = (const float*)d_in[9];
    const float* bt1 = (const float*)d_in[10];
    const float* Wt2 = (const float*)d_in[11];
    const float* bt2 = (const float*)d_in[12];
    const float* Wt3 = (const float*)d_in[13];
    const float* bt3 = (const float*)d_in[14];
    const float* Wt4 = (const float*)d_in[15];
    const float* bt4 = (const float*)d_in[16];
    const float* Wo  = (const float*)d_in[17];
    const float* bo  = (const float*)d_in[18];
    float* out = (float*)d_out;

    float *p_h1, *p_h2, *p_dense, *p_x0, *p_t1, *p_t2, *p_Wt1p;
    cudaGetSymbolAddress((void**)&p_h1, g_h1);
    cudaGetSymbolAddress((void**)&p_h2, g_h2);
    cudaGetSymbolAddress((void**)&p_dense, g_dense);
    cudaGetSymbolAddress((void**)&p_x0, g_x0);
    cudaGetSymbolAddress((void**)&p_t1, g_t1);
    cudaGetSymbolAddress((void**)&p_t2, g_t2);
    cudaGetSymbolAddress((void**)&p_Wt1p, g_Wt1p);

    // 0. detect cat_idx dtype (int32 vs int64)
    detect_idx_kernel<<<1, 256>>>((const unsigned int*)cat_idx);

    // 1. bottom MLP layer 1: dense_x (B x 13) -> g_h1 (B x 512)
    dense1_kernel<<<BATCH / 4, 128>>>(dense_x, Wd1, bd1);

    // 2. h1 @ Wd2 -> g_h2 (B x 256)
    sgemm_bias_act<<<dim3(256 / 128, BATCH / 128), 256>>>(
        p_h1, 512, Wd2, bd2, p_h2, 256, (float*)0, 0, 256, 512, 1);

    // 3. h2 @ Wdf -> g_dense (B x 128) AND g_x0[:, 351:479]
    sgemm_bias_act<<<dim3(128 / 128, BATCH / 128), 256>>>(
        p_h2, 256, Wdf, bdf, p_dense, 128, p_x0 + N_PAIRS, X0_LD, 128, 256, 1);

    // 4. pad Wt1 K: 479 -> 480
    pad_wt1_kernel<<<(X0_LD * 1024) / 256, 256>>>(Wt1);

    // 5. fused embedding gather + pairwise interactions -> g_x0[:, 0:351]
    interact_kernel<<<BATCH, 384>>>(cat_idx, emb);

    // 6. top MLP
    sgemm_bias_act<<<dim3(1024 / 128, BATCH / 128), 256>>>(
        p_x0, X0_LD, p_Wt1p, bt1, p_t1, 1024, (float*)0, 0, 1024, X0_LD, 1);
    sgemm_bias_act<<<dim3(1024 / 128, BATCH / 128), 256>>>(
        p_t1, 1024, Wt2, bt2, p_t2, 1024, (float*)0, 0, 1024, 1024, 1);
    sgemm_bias_act<<<dim3(512 / 128, BATCH / 128), 256>>>(
        p_t2, 1024, Wt3, bt3, p_h1, 512, (float*)0, 0, 512, 1024, 1);   // t3 in g_h1
    sgemm_bias_act<<<dim3(256 / 128, BATCH / 128), 256>>>(
        p_h1, 512, Wt4, bt4, p_h2, 256, (float*)0, 0, 256, 512, 1);     // t4 in g_h2

    // 7. t4 @ Wo + bo -> sigmoid -> out (B x 1)
    final_kernel<<<BATCH / 8, 256>>>(Wo, bo, out);
}